// round 1
// baseline (speedup 1.0000x reference)
#include <cuda_runtime.h>
#include <math.h>

#define B 2
#define L 2048
#define HID 512
#define NH 8
#define HD 64
#define SAMPLE_K 40
#define N_TOP 40

// ---------------- scratch (static device globals; no allocations) ----------
__device__ float g_q[B * L * HID];
__device__ float g_k[B * L * HID];
__device__ float g_v[B * L * HID];
__device__ float g_ctx[B * L * HID];
__device__ float g_m[B * NH * L];
__device__ int   g_mtop[B * NH * N_TOP];
__device__ float g_vmean[B * NH * HD];
__device__ float g_ctxsel[B * NH * N_TOP * HD];

// ---------------- tiled SGEMM: C[m,n] = sum_k A[m,k] * W[n,k] + bias[n] ----
// A: (M,K) row-major, W: (N,K) row-major (i.e. we multiply by W^T), C: (M,N)
#define BM 64
#define BN 64
#define BK 16

__global__ void sgemm_wt_bias(const float* __restrict__ A,
                              const float* __restrict__ W,
                              const float* __restrict__ bias,
                              float* __restrict__ C,
                              int M, int N, int K) {
    __shared__ float As[BK][BM + 1];
    __shared__ float Ws[BK][BN + 1];

    const int tx = threadIdx.x % 16;   // n-direction
    const int ty = threadIdx.x / 16;   // m-direction
    const int m0 = blockIdx.y * BM;
    const int n0 = blockIdx.x * BN;

    const int lr = threadIdx.x / 16;   // 0..15 (row within 16-row group)
    const int lc = threadIdx.x % 16;   // 0..15 (k index)

    float acc[4][4];
#pragma unroll
    for (int i = 0; i < 4; i++)
#pragma unroll
        for (int j = 0; j < 4; j++) acc[i][j] = 0.0f;

    for (int k0 = 0; k0 < K; k0 += BK) {
#pragma unroll
        for (int i = 0; i < 4; i++) {
            As[lc][lr + 16 * i] = A[(size_t)(m0 + lr + 16 * i) * K + k0 + lc];
            Ws[lc][lr + 16 * i] = W[(size_t)(n0 + lr + 16 * i) * K + k0 + lc];
        }
        __syncthreads();
#pragma unroll
        for (int kk = 0; kk < BK; kk++) {
            float a[4], w[4];
#pragma unroll
            for (int i = 0; i < 4; i++) a[i] = As[kk][ty * 4 + i];
#pragma unroll
            for (int j = 0; j < 4; j++) w[j] = Ws[kk][tx * 4 + j];
#pragma unroll
            for (int i = 0; i < 4; i++)
#pragma unroll
                for (int j = 0; j < 4; j++) acc[i][j] += a[i] * w[j];
        }
        __syncthreads();
    }

#pragma unroll
    for (int i = 0; i < 4; i++) {
        int m = m0 + ty * 4 + i;
#pragma unroll
        for (int j = 0; j < 4; j++) {
            int n = n0 + tx * 4 + j;
            C[(size_t)m * N + n] = acc[i][j] + bias[n];
        }
    }
}

// ---------------- m-score: m[b,h,l] = max_s(qk) - sum_s(qk)/L ---------------
// one warp per (b,h,l). q,k stored as (B,L,HID) with head h at cols h*HD.
__global__ void mscore_kernel(const int* __restrict__ idx_sample) {
    int warp = (blockIdx.x * blockDim.x + threadIdx.x) >> 5;
    int lane = threadIdx.x & 31;
    if (warp >= B * NH * L) return;
    int l = warp % L;
    int h = (warp / L) % NH;
    int b = warp / (L * NH);

    const float* qrow = g_q + ((size_t)b * L + l) * HID + h * HD;
    float q0 = qrow[lane];
    float q1 = qrow[lane + 32];

    float mx = -INFINITY, sm = 0.0f;
#pragma unroll 4
    for (int s = 0; s < SAMPLE_K; s++) {
        int ls = idx_sample[l * SAMPLE_K + s];
        const float* krow = g_k + ((size_t)b * L + ls) * HID + h * HD;
        float d = q0 * krow[lane] + q1 * krow[lane + 32];
#pragma unroll
        for (int o = 16; o; o >>= 1) d += __shfl_xor_sync(0xffffffffu, d, o);
        mx = fmaxf(mx, d);
        sm += d;
    }
    if (lane == 0) g_m[warp] = mx - sm * (1.0f / (float)L);
}

// ---------------- top-k via iterative argmax: one block per (b,h) ----------
__global__ void topk_kernel() {
    int bh = blockIdx.x;  // b*NH + h
    __shared__ float sval[L];
    __shared__ float rv[256];
    __shared__ int   ri[256];

    for (int i = threadIdx.x; i < L; i += 256) sval[i] = g_m[(size_t)bh * L + i];
    __syncthreads();

    for (int t = 0; t < N_TOP; t++) {
        float best = -INFINITY;
        int   bi = 0x7fffffff;
        for (int i = threadIdx.x; i < L; i += 256) {
            float v = sval[i];
            if (v > best) { best = v; bi = i; }
        }
        rv[threadIdx.x] = best;
        ri[threadIdx.x] = bi;
        __syncthreads();
        for (int s = 128; s; s >>= 1) {
            if (threadIdx.x < s) {
                float ov = rv[threadIdx.x + s];
                int   oi = ri[threadIdx.x + s];
                if (ov > rv[threadIdx.x] ||
                    (ov == rv[threadIdx.x] && oi < ri[threadIdx.x])) {
                    rv[threadIdx.x] = ov;
                    ri[threadIdx.x] = oi;
                }
            }
            __syncthreads();
        }
        if (threadIdx.x == 0) {
            g_mtop[bh * N_TOP + t] = ri[0];
            sval[ri[0]] = -INFINITY;
        }
        __syncthreads();
    }
}

// ---------------- v mean over L: one block per (b,h) ----------------------
__global__ void vmean_kernel() {
    int bh = blockIdx.x;
    int b = bh / NH, h = bh % NH;
    int d = threadIdx.x % HD;
    int g = threadIdx.x / HD;  // 0..3
    float s = 0.0f;
    for (int l = g; l < L; l += 4)
        s += g_v[((size_t)b * L + l) * HID + h * HD + d];
    __shared__ float sh[256];
    sh[threadIdx.x] = s;
    __syncthreads();
    if (g == 0)
        g_vmean[bh * HD + d] =
            (sh[d] + sh[d + 64] + sh[d + 128] + sh[d + 192]) * (1.0f / (float)L);
}

// ---------------- selected attention: one block per (b,h,qi) ---------------
__global__ void attn_kernel() {
    int blk = blockIdx.x;
    int qi = blk % N_TOP;
    int h  = (blk / N_TOP) % NH;
    int b  = blk / (N_TOP * NH);

    __shared__ float sq[HD];
    __shared__ float sc[L];
    __shared__ float red[256];

    int lq = g_mtop[(b * NH + h) * N_TOP + qi];
    if (threadIdx.x < HD)
        sq[threadIdx.x] = g_q[((size_t)b * L + lq) * HID + h * HD + threadIdx.x];
    __syncthreads();

    int lane = threadIdx.x & 31, w = threadIdx.x >> 5;
    // scores (warp per key, 8 warps stride over L)
    for (int key = w; key < L; key += 8) {
        const float* krow = g_k + ((size_t)b * L + key) * HID + h * HD;
        float d = sq[lane] * krow[lane] + sq[lane + 32] * krow[lane + 32];
#pragma unroll
        for (int o = 16; o; o >>= 1) d += __shfl_xor_sync(0xffffffffu, d, o);
        if (lane == 0) sc[key] = d * 0.125f;  // 1/sqrt(64)
    }
    __syncthreads();

    // softmax over L
    float mx = -INFINITY;
    for (int i = threadIdx.x; i < L; i += 256) mx = fmaxf(mx, sc[i]);
    red[threadIdx.x] = mx;
    __syncthreads();
    for (int s = 128; s; s >>= 1) {
        if (threadIdx.x < s)
            red[threadIdx.x] = fmaxf(red[threadIdx.x], red[threadIdx.x + s]);
        __syncthreads();
    }
    mx = red[0];
    __syncthreads();

    float se = 0.0f;
    for (int i = threadIdx.x; i < L; i += 256) {
        float e = expf(sc[i] - mx);
        sc[i] = e;
        se += e;
    }
    red[threadIdx.x] = se;
    __syncthreads();
    for (int s = 128; s; s >>= 1) {
        if (threadIdx.x < s) red[threadIdx.x] += red[threadIdx.x + s];
        __syncthreads();
    }
    float inv = 1.0f / red[0];
    __syncthreads();

    // ctx[d] = sum_key p[key] * v[key, d]
    int d = threadIdx.x % HD;
    int g = threadIdx.x / HD;  // 0..3
    float acc = 0.0f;
    for (int key = g; key < L; key += 4)
        acc += sc[key] * g_v[((size_t)b * L + key) * HID + h * HD + d];
    red[threadIdx.x] = acc;
    __syncthreads();
    if (g == 0)
        g_ctxsel[((size_t)(b * NH + h) * N_TOP + qi) * HD + d] =
            (red[d] + red[d + 64] + red[d + 128] + red[d + 192]) * inv;
}

// ---------------- context assembly ----------------------------------------
__global__ void ctx_build_kernel() {
    int i = blockIdx.x * blockDim.x + threadIdx.x;
    if (i >= B * L * HID) return;
    int d = i % HD;
    int h = (i / HD) % NH;
    int b = i / (HID * L);
    g_ctx[i] = g_vmean[(b * NH + h) * HD + d];
}

__global__ void ctx_scatter_kernel() {
    int i = blockIdx.x * blockDim.x + threadIdx.x;
    if (i >= B * NH * N_TOP * HD) return;
    int d  = i % HD;
    int qi = (i / HD) % N_TOP;
    int h  = (i / (HD * N_TOP)) % NH;
    int b  = i / (HD * N_TOP * NH);
    int l  = g_mtop[(b * NH + h) * N_TOP + qi];
    g_ctx[((size_t)b * L + l) * HID + h * HD + d] = g_ctxsel[i];
}

// ---------------- launch ----------------------------------------------------
extern "C" void kernel_launch(void* const* d_in, const int* in_sizes, int n_in,
                              void* d_out, int out_size) {
    const float* hidden = (const float*)d_in[0];
    const int*   idxs   = (const int*)d_in[1];
    const float* Wq = (const float*)d_in[2];
    const float* bq = (const float*)d_in[3];
    const float* Wk = (const float*)d_in[4];
    const float* bk = (const float*)d_in[5];
    const float* Wv = (const float*)d_in[6];
    const float* bv = (const float*)d_in[7];
    const float* Wo = (const float*)d_in[8];
    const float* bo = (const float*)d_in[9];
    float* out = (float*)d_out;

    float *pq, *pk, *pv, *pctx;
    cudaGetSymbolAddress((void**)&pq, g_q);
    cudaGetSymbolAddress((void**)&pk, g_k);
    cudaGetSymbolAddress((void**)&pv, g_v);
    cudaGetSymbolAddress((void**)&pctx, g_ctx);

    const int M = B * L;  // 4096
    dim3 gemm_grid(HID / BN, M / BM);  // (8, 64)
    dim3 gemm_blk(256);

    // Q, K, V projections
    sgemm_wt_bias<<<gemm_grid, gemm_blk>>>(hidden, Wq, bq, pq, M, HID, HID);
    sgemm_wt_bias<<<gemm_grid, gemm_blk>>>(hidden, Wk, bk, pk, M, HID, HID);
    sgemm_wt_bias<<<gemm_grid, gemm_blk>>>(hidden, Wv, bv, pv, M, HID, HID);

    // m scores: one warp per (b,h,l) -> B*NH*L warps, 8 warps per block
    mscore_kernel<<<(B * NH * L) / 8, 256>>>(idxs);

    // top-k per (b,h)
    topk_kernel<<<B * NH, 256>>>();

    // v mean per (b,h)
    vmean_kernel<<<B * NH, 256>>>();

    // selected attention
    attn_kernel<<<B * NH * N_TOP, 256>>>();

    // context assembly
    ctx_build_kernel<<<(B * L * HID + 255) / 256, 256>>>();
    ctx_scatter_kernel<<<(B * NH * N_TOP * HD + 255) / 256, 256>>>();

    // output projection
    sgemm_wt_bias<<<gemm_grid, gemm_blk>>>(pctx, Wo, bo, out, M, HID, HID);
}

// round 3
// speedup vs baseline: 1.8880x; 1.8880x over previous
#include <cuda_runtime.h>
#include <cuda_bf16.h>
#include <math.h>
#include <stdint.h>

#define B 2
#define L 2048
#define HID 512
#define NH 8
#define HD 64
#define SAMPLE_K 40
#define N_TOP 40

// ===================== helpers ==============================================
__device__ __forceinline__ uint32_t smem_u32(const void* p) {
    uint32_t a;
    asm("{ .reg .u64 t; cvta.to.shared.u64 t, %1; cvt.u32.u64 %0, t; }"
        : "=r"(a) : "l"(p));
    return a;
}

// ===================== scratch ==============================================
__device__ float g_q[B * L * HID];
__device__ float g_k[B * L * HID];
__device__ float g_v[B * L * HID];
__device__ float g_ctx[B * L * HID];
__device__ float g_m[B * NH * L];
__device__ int   g_mtop[B * NH * N_TOP];
__device__ float g_vmean[B * NH * HD];
__device__ float g_ctxsel[B * NH * N_TOP * HD];
// bf16 hi/lo splits
__device__ __nv_bfloat16 g_ah[B * L * HID];
__device__ __nv_bfloat16 g_al[B * L * HID];
__device__ __nv_bfloat16 g_wh[3 * HID * HID];
__device__ __nv_bfloat16 g_wl[3 * HID * HID];
__device__ __nv_bfloat16 g_oh[HID * HID];
__device__ __nv_bfloat16 g_ol[HID * HID];
__device__ __nv_bfloat16 g_ch[B * L * HID];
__device__ __nv_bfloat16 g_cl[B * L * HID];

// ===================== fp32 -> bf16 hi/lo split =============================
__global__ void split_bf16(const float* __restrict__ x,
                           __nv_bfloat16* __restrict__ hi,
                           __nv_bfloat16* __restrict__ lo, int n) {
    int i = blockIdx.x * blockDim.x + threadIdx.x;
    if (i >= n) return;
    float v = x[i];
    __nv_bfloat16 h = __float2bfloat16(v);
    hi[i] = h;
    lo[i] = __float2bfloat16(v - __bfloat162float(h));
}

// ===================== HMMA split-bf16 GEMM =================================
// C[m, n_local] = sum_k A[m,k] * Bmat[n_global, k] + bias[n_local]
// A split (Ah,Al) [M x 512] bf16; B split (Bh,Bl) row-major [n, k].
// QKV fused: gridDim.x = 12, sel = blockIdx.x>>2 selects (bias,out).
#define TM 128
#define TN 128
#define KC 32
#define NCH (HID / KC)                 // 16
#define TILE_B (TM * KC * 2)           // 8192 bytes per tile
#define STAGE_B (4 * TILE_B)           // Ah, Al, Bh, Bl
#define NSTG 3
#define GEMM_SMEM (NSTG * STAGE_B)     // 98304

// swizzled offset within a [128 x 32] bf16 tile (64B rows, SW64-style)
__device__ __forceinline__ uint32_t swz(uint32_t off) {
    return off ^ ((off >> 3) & 0x30);
}

// ldmatrix x4 of a 16-row x 16-col bf16 block at (rowbase, ks*16) of a tile
__device__ __forceinline__ void ldsm4(uint32_t r[4], uint32_t tile,
                                      int rowbase, int ks) {
    int lane = threadIdx.x & 31;
    int row = rowbase + (lane & 15);
    int c16 = ks * 2 + (lane >> 4);
    uint32_t addr = tile + swz((uint32_t)(row * 64 + c16 * 16));
    asm volatile("ldmatrix.sync.aligned.m8n8.x4.shared.b16 {%0,%1,%2,%3}, [%4];"
                 : "=r"(r[0]), "=r"(r[1]), "=r"(r[2]), "=r"(r[3]) : "r"(addr));
}

__device__ __forceinline__ void mma16816(float c[4], const uint32_t a[4],
                                         uint32_t b0, uint32_t b1) {
    asm volatile(
        "mma.sync.aligned.m16n8k16.row.col.f32.bf16.bf16.f32 "
        "{%0,%1,%2,%3},{%4,%5,%6,%7},{%8,%9},{%0,%1,%2,%3};"
        : "+f"(c[0]), "+f"(c[1]), "+f"(c[2]), "+f"(c[3])
        : "r"(a[0]), "r"(a[1]), "r"(a[2]), "r"(a[3]), "r"(b0), "r"(b1));
}

__global__ void __launch_bounds__(256, 1)
gemm_hmma_split(const __nv_bfloat16* __restrict__ Ah,
                const __nv_bfloat16* __restrict__ Al,
                const __nv_bfloat16* __restrict__ Bh,
                const __nv_bfloat16* __restrict__ Bl,
                const float* __restrict__ b0p, const float* __restrict__ b1p,
                const float* __restrict__ b2p,
                float* __restrict__ o0, float* __restrict__ o1,
                float* __restrict__ o2) {
    extern __shared__ char smem[];
    const uint32_t sbase = smem_u32(smem);

    const int tid = threadIdx.x;
    const int wid = tid >> 5;
    const int lane = tid & 31;
    const int wm = wid >> 2;   // 0..1
    const int wn = wid & 3;    // 0..3

    const int m0 = blockIdx.y * TM;
    const int n0g = blockIdx.x * TN;
    const int sel = blockIdx.x >> 2;
    const int n0l = (blockIdx.x & 3) * TN;
    const float* bias = sel == 0 ? b0p : (sel == 1 ? b1p : b2p);
    float* out = sel == 0 ? o0 : (sel == 1 ? o1 : o2);

    const __nv_bfloat16* srcs[4] = {Ah, Al, Bh, Bl};

    float acc[4][4][4];
#pragma unroll
    for (int i = 0; i < 4; i++)
#pragma unroll
        for (int j = 0; j < 4; j++)
#pragma unroll
            for (int t = 0; t < 4; t++) acc[i][j][t] = 0.0f;

    // ---- async tile loader: chunk c into stage stg ----
    auto load_chunk = [&](int c, int stg) {
        const int k0 = c * KC;
#pragma unroll
        for (int t = 0; t < 4; t++) {
            const int rowbase = (t < 2) ? m0 : n0g;
            const uint32_t tile = sbase + stg * STAGE_B + t * TILE_B;
#pragma unroll
            for (int i = 0; i < 2; i++) {
                int idx = tid + i * 256;     // 0..511
                int row = idx >> 2;
                int c16 = idx & 3;
                const void* src =
                    srcs[t] + (size_t)(rowbase + row) * HID + k0 + c16 * 8;
                uint32_t dst = tile + swz((uint32_t)(row * 64 + c16 * 16));
                asm volatile("cp.async.cg.shared.global [%0], [%1], 16;"
                             :: "r"(dst), "l"(src));
            }
        }
    };

    load_chunk(0, 0);
    asm volatile("cp.async.commit_group;" ::: "memory");
    load_chunk(1, 1);
    asm volatile("cp.async.commit_group;" ::: "memory");

    for (int c = 0; c < NCH; c++) {
        if (c + 2 < NCH) load_chunk(c + 2, (c + 2) % NSTG);
        asm volatile("cp.async.commit_group;" ::: "memory");
        asm volatile("cp.async.wait_group 2;" ::: "memory");
        __syncthreads();

        const uint32_t stg = sbase + (c % NSTG) * STAGE_B;
        const uint32_t tAh = stg;
        const uint32_t tAl = stg + TILE_B;
        const uint32_t tBh = stg + 2 * TILE_B;
        const uint32_t tBl = stg + 3 * TILE_B;

#pragma unroll
        for (int ks = 0; ks < 2; ks++) {
            uint32_t ah[4][4], al[4][4], bh[2][4], bl[2][4];
#pragma unroll
            for (int mf = 0; mf < 4; mf++) {
                ldsm4(ah[mf], tAh, wm * 64 + mf * 16, ks);
                ldsm4(al[mf], tAl, wm * 64 + mf * 16, ks);
            }
#pragma unroll
            for (int p = 0; p < 2; p++) {
                ldsm4(bh[p], tBh, wn * 32 + p * 16, ks);
                ldsm4(bl[p], tBl, wn * 32 + p * 16, ks);
            }
#pragma unroll
            for (int mf = 0; mf < 4; mf++) {
#pragma unroll
                for (int nf = 0; nf < 4; nf++) {
                    int p = nf >> 1, q = nf & 1;
                    mma16816(acc[mf][nf], ah[mf], bh[p][q], bh[p][q + 2]);
                    mma16816(acc[mf][nf], ah[mf], bl[p][q], bl[p][q + 2]);
                    mma16816(acc[mf][nf], al[mf], bh[p][q], bh[p][q + 2]);
                }
            }
        }
        __syncthreads();
    }

    // ---- epilogue: acc + bias -> out ----
    const int r0 = m0 + wm * 64;
    const int c0 = n0l + wn * 32;
#pragma unroll
    for (int mf = 0; mf < 4; mf++) {
#pragma unroll
        for (int nf = 0; nf < 4; nf++) {
            int row = r0 + mf * 16 + (lane >> 2);
            int col = c0 + nf * 8 + (lane & 3) * 2;
            float bu0 = bias[col], bu1 = bias[col + 1];
            out[(size_t)row * HID + col]           = acc[mf][nf][0] + bu0;
            out[(size_t)row * HID + col + 1]       = acc[mf][nf][1] + bu1;
            out[(size_t)(row + 8) * HID + col]     = acc[mf][nf][2] + bu0;
            out[(size_t)(row + 8) * HID + col + 1] = acc[mf][nf][3] + bu1;
        }
    }
}

// ===================== m-score ==============================================
__global__ void mscore_kernel(const int* __restrict__ idx_sample) {
    int warp = (blockIdx.x * blockDim.x + threadIdx.x) >> 5;
    int lane = threadIdx.x & 31;
    if (warp >= B * NH * L) return;
    int l = warp % L;
    int h = (warp / L) % NH;
    int b = warp / (L * NH);

    const float* qrow = g_q + ((size_t)b * L + l) * HID + h * HD;
    float q0 = qrow[lane];
    float q1 = qrow[lane + 32];

    float mx = -INFINITY, sm = 0.0f;
#pragma unroll 4
    for (int s = 0; s < SAMPLE_K; s++) {
        int ls = idx_sample[l * SAMPLE_K + s];
        const float* krow = g_k + ((size_t)b * L + ls) * HID + h * HD;
        float d = q0 * krow[lane] + q1 * krow[lane + 32];
#pragma unroll
        for (int o = 16; o; o >>= 1) d += __shfl_xor_sync(0xffffffffu, d, o);
        mx = fmaxf(mx, d);
        sm += d;
    }
    if (lane == 0) g_m[warp] = mx - sm * (1.0f / (float)L);
}

// ===================== top-k ================================================
__global__ void topk_kernel() {
    int bh = blockIdx.x;
    __shared__ float sval[L];
    __shared__ float rv[256];
    __shared__ int ri[256];

    for (int i = threadIdx.x; i < L; i += 256) sval[i] = g_m[(size_t)bh * L + i];
    __syncthreads();

    for (int t = 0; t < N_TOP; t++) {
        float best = -INFINITY;
        int bi = 0x7fffffff;
        for (int i = threadIdx.x; i < L; i += 256) {
            float v = sval[i];
            if (v > best) { best = v; bi = i; }
        }
        rv[threadIdx.x] = best;
        ri[threadIdx.x] = bi;
        __syncthreads();
        for (int s = 128; s; s >>= 1) {
            if (threadIdx.x < s) {
                float ov = rv[threadIdx.x + s];
                int oi = ri[threadIdx.x + s];
                if (ov > rv[threadIdx.x] ||
                    (ov == rv[threadIdx.x] && oi < ri[threadIdx.x])) {
                    rv[threadIdx.x] = ov;
                    ri[threadIdx.x] = oi;
                }
            }
            __syncthreads();
        }
        if (threadIdx.x == 0) {
            g_mtop[bh * N_TOP + t] = ri[0];
            sval[ri[0]] = -INFINITY;
        }
        __syncthreads();
    }
}

// ===================== v mean ===============================================
__global__ void vmean_kernel() {
    int bh = blockIdx.x;
    int b = bh / NH, h = bh % NH;
    int d = threadIdx.x % HD;
    int g = threadIdx.x / HD;
    float s = 0.0f;
    for (int l = g; l < L; l += 4)
        s += g_v[((size_t)b * L + l) * HID + h * HD + d];
    __shared__ float sh[256];
    sh[threadIdx.x] = s;
    __syncthreads();
    if (g == 0)
        g_vmean[bh * HD + d] =
            (sh[d] + sh[d + 64] + sh[d + 128] + sh[d + 192]) * (1.0f / (float)L);
}

// ===================== selected attention ===================================
__global__ void attn_kernel() {
    int blk = blockIdx.x;
    int qi = blk % N_TOP;
    int h = (blk / N_TOP) % NH;
    int b = blk / (N_TOP * NH);

    __shared__ float sq[HD];
    __shared__ float sc[L];
    __shared__ float red[256];

    int lq = g_mtop[(b * NH + h) * N_TOP + qi];
    if (threadIdx.x < HD)
        sq[threadIdx.x] = g_q[((size_t)b * L + lq) * HID + h * HD + threadIdx.x];
    __syncthreads();

    int lane = threadIdx.x & 31, w = threadIdx.x >> 5;
    for (int key = w; key < L; key += 8) {
        const float* krow = g_k + ((size_t)b * L + key) * HID + h * HD;
        float d = sq[lane] * krow[lane] + sq[lane + 32] * krow[lane + 32];
#pragma unroll
        for (int o = 16; o; o >>= 1) d += __shfl_xor_sync(0xffffffffu, d, o);
        if (lane == 0) sc[key] = d * 0.125f;
    }
    __syncthreads();

    float mx = -INFINITY;
    for (int i = threadIdx.x; i < L; i += 256) mx = fmaxf(mx, sc[i]);
    red[threadIdx.x] = mx;
    __syncthreads();
    for (int s = 128; s; s >>= 1) {
        if (threadIdx.x < s)
            red[threadIdx.x] = fmaxf(red[threadIdx.x], red[threadIdx.x + s]);
        __syncthreads();
    }
    mx = red[0];
    __syncthreads();

    float se = 0.0f;
    for (int i = threadIdx.x; i < L; i += 256) {
        float e = expf(sc[i] - mx);
        sc[i] = e;
        se += e;
    }
    red[threadIdx.x] = se;
    __syncthreads();
    for (int s = 128; s; s >>= 1) {
        if (threadIdx.x < s) red[threadIdx.x] += red[threadIdx.x + s];
        __syncthreads();
    }
    float inv = 1.0f / red[0];
    __syncthreads();

    int d = threadIdx.x % HD;
    int g = threadIdx.x / HD;
    float acc = 0.0f;
    for (int key = g; key < L; key += 4)
        acc += sc[key] * g_v[((size_t)b * L + key) * HID + h * HD + d];
    red[threadIdx.x] = acc;
    __syncthreads();
    if (g == 0)
        g_ctxsel[((size_t)(b * NH + h) * N_TOP + qi) * HD + d] =
            (red[d] + red[d + 64] + red[d + 128] + red[d + 192]) * inv;
}

// ===================== context assembly =====================================
__global__ void ctx_build_kernel() {
    int i = blockIdx.x * blockDim.x + threadIdx.x;
    if (i >= B * L * HID) return;
    int d = i % HD;
    int h = (i / HD) % NH;
    int b = i / (HID * L);
    g_ctx[i] = g_vmean[(b * NH + h) * HD + d];
}

__global__ void ctx_scatter_kernel() {
    int i = blockIdx.x * blockDim.x + threadIdx.x;
    if (i >= B * NH * N_TOP * HD) return;
    int d = i % HD;
    int qi = (i / HD) % N_TOP;
    int h = (i / (HD * N_TOP)) % NH;
    int b = i / (HD * N_TOP * NH);
    int l = g_mtop[(b * NH + h) * N_TOP + qi];
    g_ctx[((size_t)b * L + l) * HID + h * HD + d] = g_ctxsel[i];
}

// ===================== launch ===============================================
extern "C" void kernel_launch(void* const* d_in, const int* in_sizes, int n_in,
                              void* d_out, int out_size) {
    const float* hidden = (const float*)d_in[0];
    const int* idxs = (const int*)d_in[1];
    const float* Wq = (const float*)d_in[2];
    const float* bq = (const float*)d_in[3];
    const float* Wk = (const float*)d_in[4];
    const float* bk = (const float*)d_in[5];
    const float* Wv = (const float*)d_in[6];
    const float* bv = (const float*)d_in[7];
    const float* Wo = (const float*)d_in[8];
    const float* bo = (const float*)d_in[9];
    float* out = (float*)d_out;

    float *pq, *pk, *pv, *pctx;
    cudaGetSymbolAddress((void**)&pq, g_q);
    cudaGetSymbolAddress((void**)&pk, g_k);
    cudaGetSymbolAddress((void**)&pv, g_v);
    cudaGetSymbolAddress((void**)&pctx, g_ctx);
    __nv_bfloat16 *pah, *pal, *pwh, *pwl, *poh, *pol, *pch, *pcl;
    cudaGetSymbolAddress((void**)&pah, g_ah);
    cudaGetSymbolAddress((void**)&pal, g_al);
    cudaGetSymbolAddress((void**)&pwh, g_wh);
    cudaGetSymbolAddress((void**)&pwl, g_wl);
    cudaGetSymbolAddress((void**)&poh, g_oh);
    cudaGetSymbolAddress((void**)&pol, g_ol);
    cudaGetSymbolAddress((void**)&pch, g_ch);
    cudaGetSymbolAddress((void**)&pcl, g_cl);

    cudaFuncSetAttribute(gemm_hmma_split,
                         cudaFuncAttributeMaxDynamicSharedMemorySize, GEMM_SMEM);

    const int NW = HID * HID;  // 262144

    // splits
    split_bf16<<<(B * L * HID + 255) / 256, 256>>>(hidden, pah, pal, B * L * HID);
    split_bf16<<<(NW + 255) / 256, 256>>>(Wq, pwh, pwl, NW);
    split_bf16<<<(NW + 255) / 256, 256>>>(Wk, pwh + NW, pwl + NW, NW);
    split_bf16<<<(NW + 255) / 256, 256>>>(Wv, pwh + 2 * NW, pwl + 2 * NW, NW);
    split_bf16<<<(NW + 255) / 256, 256>>>(Wo, poh, pol, NW);

    // fused Q,K,V projection on tensor cores (HMMA)
    dim3 qkv_grid(12, (B * L) / TM);  // (12, 32)
    gemm_hmma_split<<<qkv_grid, 256, GEMM_SMEM>>>(pah, pal, pwh, pwl,
                                                  bq, bk, bv, pq, pk, pv);

    mscore_kernel<<<(B * NH * L) / 8, 256>>>(idxs);
    topk_kernel<<<B * NH, 256>>>();
    vmean_kernel<<<B * NH, 256>>>();
    attn_kernel<<<B * NH * N_TOP, 256>>>();
    ctx_build_kernel<<<(B * L * HID + 255) / 256, 256>>>();
    ctx_scatter_kernel<<<(B * NH * N_TOP * HD + 255) / 256, 256>>>();

    // output projection
    split_bf16<<<(B * L * HID + 255) / 256, 256>>>(pctx, pch, pcl, B * L * HID);
    dim3 o_grid(4, (B * L) / TM);
    gemm_hmma_split<<<o_grid, 256, GEMM_SMEM>>>(pch, pcl, poh, pol,
                                                bo, bo, bo, out, out, out);
}

// round 4
// speedup vs baseline: 2.3473x; 1.2432x over previous
#include <cuda_runtime.h>
#include <cuda_bf16.h>
#include <math.h>
#include <stdint.h>

#define B 2
#define L 2048
#define HID 512
#define NH 8
#define HD 64
#define SAMPLE_K 40
#define N_TOP 40
#define QG 8   // queries per attention block

// ===================== helpers ==============================================
__device__ __forceinline__ uint32_t smem_u32(const void* p) {
    uint32_t a;
    asm("{ .reg .u64 t; cvta.to.shared.u64 t, %1; cvt.u32.u64 %0, t; }"
        : "=r"(a) : "l"(p));
    return a;
}

// ===================== scratch ==============================================
__device__ float g_q[B * L * HID];
__device__ float g_k[B * L * HID];
__device__ float g_v[B * L * HID];
__device__ float g_m[B * NH * L];
__device__ int   g_mtop[B * NH * N_TOP];
__device__ float g_vmean[B * NH * HD];
__device__ float g_ctxsel[B * NH * N_TOP * HD];
// bf16 hi/lo splits
__device__ __nv_bfloat16 g_ah[B * L * HID];
__device__ __nv_bfloat16 g_al[B * L * HID];
__device__ __nv_bfloat16 g_wh[4 * HID * HID];   // Wq,Wk,Wv,Wo
__device__ __nv_bfloat16 g_wl[4 * HID * HID];
__device__ __nv_bfloat16 g_ch[B * L * HID];     // ctx hi/lo
__device__ __nv_bfloat16 g_cl[B * L * HID];

// ===================== fp32 -> bf16 hi/lo split (float4) ====================
__device__ __forceinline__ void split4_store(float4 v, __nv_bfloat16* hi,
                                             __nv_bfloat16* lo, size_t i4) {
    __nv_bfloat16 h0 = __float2bfloat16(v.x);
    __nv_bfloat16 h1 = __float2bfloat16(v.y);
    __nv_bfloat16 h2 = __float2bfloat16(v.z);
    __nv_bfloat16 h3 = __float2bfloat16(v.w);
    __nv_bfloat162* hp = (__nv_bfloat162*)(hi + i4 * 4);
    __nv_bfloat162* lp = (__nv_bfloat162*)(lo + i4 * 4);
    hp[0] = __nv_bfloat162(h0, h1);
    hp[1] = __nv_bfloat162(h2, h3);
    lp[0] = __nv_bfloat162(__float2bfloat16(v.x - __bfloat162float(h0)),
                           __float2bfloat16(v.y - __bfloat162float(h1)));
    lp[1] = __nv_bfloat162(__float2bfloat16(v.z - __bfloat162float(h2)),
                           __float2bfloat16(v.w - __bfloat162float(h3)));
}

__global__ void split_vec(const float* __restrict__ x,
                          __nv_bfloat16* __restrict__ hi,
                          __nv_bfloat16* __restrict__ lo, int n4) {
    int i = blockIdx.x * blockDim.x + threadIdx.x;
    if (i >= n4) return;
    split4_store(((const float4*)x)[i], hi, lo, i);
}

// 4 weights in one launch: blockIdx.y selects source; dest offset sel*NW
__global__ void split_weights(const float* __restrict__ w0,
                              const float* __restrict__ w1,
                              const float* __restrict__ w2,
                              const float* __restrict__ w3,
                              __nv_bfloat16* __restrict__ hi,
                              __nv_bfloat16* __restrict__ lo) {
    const int NW4 = HID * HID / 4;
    int i = blockIdx.x * blockDim.x + threadIdx.x;
    if (i >= NW4) return;
    int sel = blockIdx.y;
    const float* w = sel == 0 ? w0 : (sel == 1 ? w1 : (sel == 2 ? w2 : w3));
    size_t off4 = (size_t)sel * NW4 + i;
    split4_store(((const float4*)w)[i], hi, lo, off4);
}

// ===================== HMMA split-bf16 GEMM =================================
#define TM 128
#define TN 128
#define KC 32
#define NCH (HID / KC)                 // 16
#define TILE_B (TM * KC * 2)           // 8192 bytes per tile
#define STAGE_B (4 * TILE_B)
#define NSTG 3
#define GEMM_SMEM (NSTG * STAGE_B)     // 98304

__device__ __forceinline__ uint32_t swz(uint32_t off) {
    return off ^ ((off >> 3) & 0x30);
}

__device__ __forceinline__ void ldsm4(uint32_t r[4], uint32_t tile,
                                      int rowbase, int ks) {
    int lane = threadIdx.x & 31;
    int row = rowbase + (lane & 15);
    int c16 = ks * 2 + (lane >> 4);
    uint32_t addr = tile + swz((uint32_t)(row * 64 + c16 * 16));
    asm volatile("ldmatrix.sync.aligned.m8n8.x4.shared.b16 {%0,%1,%2,%3}, [%4];"
                 : "=r"(r[0]), "=r"(r[1]), "=r"(r[2]), "=r"(r[3]) : "r"(addr));
}

__device__ __forceinline__ void mma16816(float c[4], const uint32_t a[4],
                                         uint32_t b0, uint32_t b1) {
    asm volatile(
        "mma.sync.aligned.m16n8k16.row.col.f32.bf16.bf16.f32 "
        "{%0,%1,%2,%3},{%4,%5,%6,%7},{%8,%9},{%0,%1,%2,%3};"
        : "+f"(c[0]), "+f"(c[1]), "+f"(c[2]), "+f"(c[3])
        : "r"(a[0]), "r"(a[1]), "r"(a[2]), "r"(a[3]), "r"(b0), "r"(b1));
}

__global__ void __launch_bounds__(256, 1)
gemm_hmma_split(const __nv_bfloat16* __restrict__ Ah,
                const __nv_bfloat16* __restrict__ Al,
                const __nv_bfloat16* __restrict__ Bh,
                const __nv_bfloat16* __restrict__ Bl,
                const float* __restrict__ b0p, const float* __restrict__ b1p,
                const float* __restrict__ b2p,
                float* __restrict__ o0, float* __restrict__ o1,
                float* __restrict__ o2) {
    extern __shared__ char smem[];
    const uint32_t sbase = smem_u32(smem);

    const int tid = threadIdx.x;
    const int wid = tid >> 5;
    const int lane = tid & 31;
    const int wm = wid >> 2;
    const int wn = wid & 3;

    const int m0 = blockIdx.y * TM;
    const int n0g = blockIdx.x * TN;
    const int sel = blockIdx.x >> 2;
    const int n0l = (blockIdx.x & 3) * TN;
    const float* bias = sel == 0 ? b0p : (sel == 1 ? b1p : b2p);
    float* out = sel == 0 ? o0 : (sel == 1 ? o1 : o2);

    const __nv_bfloat16* srcs[4] = {Ah, Al, Bh, Bl};

    float acc[4][4][4];
#pragma unroll
    for (int i = 0; i < 4; i++)
#pragma unroll
        for (int j = 0; j < 4; j++)
#pragma unroll
            for (int t = 0; t < 4; t++) acc[i][j][t] = 0.0f;

    auto load_chunk = [&](int c, int stg) {
        const int k0 = c * KC;
#pragma unroll
        for (int t = 0; t < 4; t++) {
            const int rowbase = (t < 2) ? m0 : n0g;
            const uint32_t tile = sbase + stg * STAGE_B + t * TILE_B;
#pragma unroll
            for (int i = 0; i < 2; i++) {
                int idx = tid + i * 256;
                int row = idx >> 2;
                int c16 = idx & 3;
                const void* src =
                    srcs[t] + (size_t)(rowbase + row) * HID + k0 + c16 * 8;
                uint32_t dst = tile + swz((uint32_t)(row * 64 + c16 * 16));
                asm volatile("cp.async.cg.shared.global [%0], [%1], 16;"
                             :: "r"(dst), "l"(src));
            }
        }
    };

    load_chunk(0, 0);
    asm volatile("cp.async.commit_group;" ::: "memory");
    load_chunk(1, 1);
    asm volatile("cp.async.commit_group;" ::: "memory");

    for (int c = 0; c < NCH; c++) {
        if (c + 2 < NCH) load_chunk(c + 2, (c + 2) % NSTG);
        asm volatile("cp.async.commit_group;" ::: "memory");
        asm volatile("cp.async.wait_group 2;" ::: "memory");
        __syncthreads();

        const uint32_t stg = sbase + (c % NSTG) * STAGE_B;
        const uint32_t tAh = stg;
        const uint32_t tAl = stg + TILE_B;
        const uint32_t tBh = stg + 2 * TILE_B;
        const uint32_t tBl = stg + 3 * TILE_B;

#pragma unroll
        for (int ks = 0; ks < 2; ks++) {
            uint32_t ah[4][4], al[4][4], bh[2][4], bl[2][4];
#pragma unroll
            for (int mf = 0; mf < 4; mf++) {
                ldsm4(ah[mf], tAh, wm * 64 + mf * 16, ks);
                ldsm4(al[mf], tAl, wm * 64 + mf * 16, ks);
            }
#pragma unroll
            for (int p = 0; p < 2; p++) {
                ldsm4(bh[p], tBh, wn * 32 + p * 16, ks);
                ldsm4(bl[p], tBl, wn * 32 + p * 16, ks);
            }
#pragma unroll
            for (int mf = 0; mf < 4; mf++) {
#pragma unroll
                for (int nf = 0; nf < 4; nf++) {
                    int p = nf >> 1, q = nf & 1;
                    mma16816(acc[mf][nf], ah[mf], bh[p][q], bh[p][q + 2]);
                    mma16816(acc[mf][nf], ah[mf], bl[p][q], bl[p][q + 2]);
                    mma16816(acc[mf][nf], al[mf], bh[p][q], bh[p][q + 2]);
                }
            }
        }
        __syncthreads();
    }

    const int r0 = m0 + wm * 64;
    const int c0 = n0l + wn * 32;
#pragma unroll
    for (int mf = 0; mf < 4; mf++) {
#pragma unroll
        for (int nf = 0; nf < 4; nf++) {
            int row = r0 + mf * 16 + (lane >> 2);
            int col = c0 + nf * 8 + (lane & 3) * 2;
            float bu0 = bias[col], bu1 = bias[col + 1];
            out[(size_t)row * HID + col]           = acc[mf][nf][0] + bu0;
            out[(size_t)row * HID + col + 1]       = acc[mf][nf][1] + bu1;
            out[(size_t)(row + 8) * HID + col]     = acc[mf][nf][2] + bu0;
            out[(size_t)(row + 8) * HID + col + 1] = acc[mf][nf][3] + bu1;
        }
    }
}

// ===================== m-score (float4, 2 samples/warp) =====================
__global__ void mscore_kernel(const int* __restrict__ idx_sample) {
    int warp = (blockIdx.x * blockDim.x + threadIdx.x) >> 5;
    int lane = threadIdx.x & 31;
    if (warp >= B * NH * L) return;
    int l = warp % L;
    int h = (warp / L) % NH;
    int b = warp / (L * NH);

    int sub = lane & 15;
    int half = lane >> 4;

    const float4* qrow =
        (const float4*)(g_q + ((size_t)b * L + l) * HID + h * HD);
    float4 q4 = qrow[sub];

    float mx = -INFINITY, sm = 0.0f;
#pragma unroll 4
    for (int it = 0; it < SAMPLE_K / 2; it++) {
        int s = 2 * it + half;
        int ls = idx_sample[l * SAMPLE_K + s];
        const float4* kr =
            (const float4*)(g_k + ((size_t)b * L + ls) * HID + h * HD);
        float4 k4 = kr[sub];
        float d = q4.x * k4.x + q4.y * k4.y + q4.z * k4.z + q4.w * k4.w;
#pragma unroll
        for (int o = 8; o; o >>= 1) d += __shfl_xor_sync(0xffffffffu, d, o);
        mx = fmaxf(mx, d);
        sm += d;
    }
    // combine halves (lane 0 even stats, lane 16 odd stats)
    float mx2 = __shfl_down_sync(0xffffffffu, mx, 16);
    float sm2 = __shfl_down_sync(0xffffffffu, sm, 16);
    if (lane == 0)
        g_m[warp] = fmaxf(mx, mx2) - (sm + sm2) * (1.0f / (float)L);
}

// ===================== top-k (shuffle argmax) ===============================
__global__ void topk_kernel() {
    int bh = blockIdx.x;
    __shared__ float sval[L];
    __shared__ float wv[8];
    __shared__ int wi[8];
    int tid = threadIdx.x, lane = tid & 31, w = tid >> 5;

    for (int i = tid; i < L; i += 256) sval[i] = g_m[(size_t)bh * L + i];
    __syncthreads();

    for (int t = 0; t < N_TOP; t++) {
        float best = -INFINITY;
        int bi = 0x7fffffff;
        for (int i = tid; i < L; i += 256) {
            float v = sval[i];
            if (v > best) { best = v; bi = i; }
        }
#pragma unroll
        for (int o = 16; o; o >>= 1) {
            float ov = __shfl_xor_sync(0xffffffffu, best, o);
            int oi = __shfl_xor_sync(0xffffffffu, bi, o);
            if (ov > best || (ov == best && oi < bi)) { best = ov; bi = oi; }
        }
        if (lane == 0) { wv[w] = best; wi[w] = bi; }
        __syncthreads();
        if (tid < 8) {
            best = wv[tid];
            bi = wi[tid];
#pragma unroll
            for (int o = 4; o; o >>= 1) {
                float ov = __shfl_xor_sync(0xffu, best, o, 8);
                int oi = __shfl_xor_sync(0xffu, bi, o, 8);
                if (ov > best || (ov == best && oi < bi)) { best = ov; bi = oi; }
            }
            if (tid == 0) {
                g_mtop[bh * N_TOP + t] = bi;
                sval[bi] = -INFINITY;
            }
        }
        __syncthreads();
    }
}

// ===================== v mean ===============================================
__global__ void vmean_kernel() {
    int bh = blockIdx.x;
    int b = bh / NH, h = bh % NH;
    int d = threadIdx.x % HD;
    int g = threadIdx.x / HD;
    float s = 0.0f;
    for (int l = g; l < L; l += 4)
        s += g_v[((size_t)b * L + l) * HID + h * HD + d];
    __shared__ float sh[256];
    sh[threadIdx.x] = s;
    __syncthreads();
    if (g == 0)
        g_vmean[bh * HD + d] =
            (sh[d] + sh[d + 64] + sh[d + 128] + sh[d + 192]) * (1.0f / (float)L);
}

// ===================== selected attention: 8 queries / block ================
// grid = B*NH*(N_TOP/QG) = 80, 256 threads, 64KB dynamic smem for scores
__global__ void __launch_bounds__(256, 1) attn_kernel() {
    extern __shared__ float sc[];           // [QG][L]
    __shared__ float sq[QG][HD];
    __shared__ float inv[QG];
    __shared__ float red[4][QG][HD];

    const int tid = threadIdx.x;
    const int lane = tid & 31;
    const int w = tid >> 5;

    const int grp = blockIdx.x % (N_TOP / QG);
    const int bh = blockIdx.x / (N_TOP / QG);
    const int h = bh % NH;
    const int b = bh / NH;
    const int q0 = grp * QG;

    // load 8 query rows
#pragma unroll
    for (int r = 0; r < 2; r++) {
        int idx = tid + r * 256;            // 0..511
        int j = idx >> 6, d = idx & 63;
        int lq = g_mtop[bh * N_TOP + q0 + j];
        sq[j][d] = g_q[((size_t)b * L + lq) * HID + h * HD + d];
    }
    __syncthreads();

    // ---- scores: half-warp per key, float4 ----
    {
        const int sub = lane & 15;
        const int half = lane >> 4;
        float4 q4[QG];
#pragma unroll
        for (int j = 0; j < QG; j++) q4[j] = *(const float4*)&sq[j][sub * 4];

        for (int base = w * 2; base < L; base += 16) {
            int key = base + half;
            const float4* kr =
                (const float4*)(g_k + ((size_t)b * L + key) * HID + h * HD);
            float4 k4 = kr[sub];
            float dj[QG];
#pragma unroll
            for (int j = 0; j < QG; j++) {
                float d = q4[j].x * k4.x + q4[j].y * k4.y +
                          q4[j].z * k4.z + q4[j].w * k4.w;
#pragma unroll
                for (int o = 8; o; o >>= 1)
                    d += __shfl_xor_sync(0xffffffffu, d, o);
                dj[j] = d * 0.125f;
            }
            if (sub == 0) {
#pragma unroll
                for (int j = 0; j < QG; j++) sc[j * L + key] = dj[j];
            }
        }
    }
    __syncthreads();

    // ---- softmax: warp w handles query row w ----
    {
        float mx = -INFINITY;
        for (int i = lane; i < L; i += 32) mx = fmaxf(mx, sc[w * L + i]);
#pragma unroll
        for (int o = 16; o; o >>= 1)
            mx = fmaxf(mx, __shfl_xor_sync(0xffffffffu, mx, o));
        float s = 0.0f;
        for (int i = lane; i < L; i += 32) {
            float e = __expf(sc[w * L + i] - mx);
            sc[w * L + i] = e;
            s += e;
        }
#pragma unroll
        for (int o = 16; o; o >>= 1) s += __shfl_xor_sync(0xffffffffu, s, o);
        if (lane == 0) inv[w] = 1.0f / s;
    }
    __syncthreads();

    // ---- ctx: P @ V, acc over keys, 4 key-groups x 64 d-threads ----
    {
        const int g = tid >> 6;
        const int d = tid & 63;
        float acc[QG];
#pragma unroll
        for (int j = 0; j < QG; j++) acc[j] = 0.0f;
        for (int key = g; key < L; key += 4) {
            float vv = g_v[((size_t)b * L + key) * HID + h * HD + d];
#pragma unroll
            for (int j = 0; j < QG; j++) acc[j] += sc[j * L + key] * vv;
        }
#pragma unroll
        for (int j = 0; j < QG; j++) red[g][j][d] = acc[j];
        __syncthreads();
        if (g == 0) {
#pragma unroll
            for (int j = 0; j < QG; j++) {
                float tot = red[0][j][d] + red[1][j][d] + red[2][j][d] +
                            red[3][j][d];
                g_ctxsel[((size_t)bh * N_TOP + q0 + j) * HD + d] =
                    tot * inv[j];
            }
        }
    }
}

// ===================== ctx assembly directly into bf16 hi/lo ================
__global__ void ctx_build_split() {
    int i4 = blockIdx.x * blockDim.x + threadIdx.x;
    if (i4 >= B * L * HID / 4) return;
    int i = i4 * 4;
    int d0 = i % HID;
    int h = d0 >> 6, d = d0 & 63;
    int b = i / (L * HID);
    float4 vm = *(const float4*)&g_vmean[(b * NH + h) * HD + d];
    split4_store(vm, g_ch, g_cl, i4);
}

__global__ void ctx_scatter_split() {
    int i4 = blockIdx.x * blockDim.x + threadIdx.x;
    if (i4 >= B * NH * N_TOP * HD / 4) return;
    int i = i4 * 4;
    int d = i % HD;
    int qi = (i / HD) % N_TOP;
    int h = (i / (HD * N_TOP)) % NH;
    int b = i / (HD * N_TOP * NH);
    float4 c = *(const float4*)&g_ctxsel[i];
    int l = g_mtop[(b * NH + h) * N_TOP + qi];
    size_t off = ((size_t)b * L + l) * HID + h * HD + d;
    split4_store(c, g_ch + off - (size_t)i4 * 4, g_cl + off - (size_t)i4 * 4, i4);
}

// ===================== launch ===============================================
extern "C" void kernel_launch(void* const* d_in, const int* in_sizes, int n_in,
                              void* d_out, int out_size) {
    const float* hidden = (const float*)d_in[0];
    const int* idxs = (const int*)d_in[1];
    const float* Wq = (const float*)d_in[2];
    const float* bq = (const float*)d_in[3];
    const float* Wk = (const float*)d_in[4];
    const float* bk = (const float*)d_in[5];
    const float* Wv = (const float*)d_in[6];
    const float* bv = (const float*)d_in[7];
    const float* Wo = (const float*)d_in[8];
    const float* bo = (const float*)d_in[9];
    float* out = (float*)d_out;

    float *pq, *pk, *pv;
    cudaGetSymbolAddress((void**)&pq, g_q);
    cudaGetSymbolAddress((void**)&pk, g_k);
    cudaGetSymbolAddress((void**)&pv, g_v);
    __nv_bfloat16 *pah, *pal, *pwh, *pwl, *pch, *pcl;
    cudaGetSymbolAddress((void**)&pah, g_ah);
    cudaGetSymbolAddress((void**)&pal, g_al);
    cudaGetSymbolAddress((void**)&pwh, g_wh);
    cudaGetSymbolAddress((void**)&pwl, g_wl);
    cudaGetSymbolAddress((void**)&pch, g_ch);
    cudaGetSymbolAddress((void**)&pcl, g_cl);

    cudaFuncSetAttribute(gemm_hmma_split,
                         cudaFuncAttributeMaxDynamicSharedMemorySize, GEMM_SMEM);
    cudaFuncSetAttribute(attn_kernel,
                         cudaFuncAttributeMaxDynamicSharedMemorySize,
                         QG * L * (int)sizeof(float));

    const int NW = HID * HID;

    // splits (vectorized)
    split_vec<<<(B * L * HID / 4 + 255) / 256, 256>>>(hidden, pah, pal,
                                                      B * L * HID / 4);
    dim3 wgrid((NW / 4 + 255) / 256, 4);
    split_weights<<<wgrid, 256>>>(Wq, Wk, Wv, Wo, pwh, pwl);

    // fused Q,K,V projection (HMMA)
    dim3 qkv_grid(12, (B * L) / TM);
    gemm_hmma_split<<<qkv_grid, 256, GEMM_SMEM>>>(pah, pal, pwh, pwl,
                                                  bq, bk, bv, pq, pk, pv);

    mscore_kernel<<<(B * NH * L) / 8, 256>>>(idxs);
    topk_kernel<<<B * NH, 256>>>();
    vmean_kernel<<<B * NH, 256>>>();
    attn_kernel<<<B * NH * (N_TOP / QG), 256, QG * L * sizeof(float)>>>();

    ctx_build_split<<<(B * L * HID / 4 + 255) / 256, 256>>>();
    ctx_scatter_split<<<(B * NH * N_TOP * HD / 4 + 255) / 256, 256>>>();

    // output projection
    dim3 o_grid(4, (B * L) / TM);
    gemm_hmma_split<<<o_grid, 256, GEMM_SMEM>>>(pch, pcl, pwh + 3 * (size_t)NW,
                                                pwl + 3 * (size_t)NW,
                                                bo, bo, bo, out, out, out);
}